// round 5
// baseline (speedup 1.0000x reference)
#include <cuda_runtime.h>
#include <cuda_bf16.h>
#include <cstdint>

// out[i] = softmax( (x2[i] @ v1^T) / 1000 ) @ x2[i],  v1 = x1@W.T + b,  N=384 everywhere.
// Scheme: P = 1/384 + delta  ->  out = colsum(x2[i])/384 + delta @ x2[i]
// GEMMs in bf16 mma.sync (m16n8k16), softmax + delta in fp32 registers.

constexpr int N = 384;
constexpr float SCALE_INV = 1.0f / 1000.0f;
constexpr float INV_N = 1.0f / 384.0f;

constexpr int QS = 392;   // sQ row stride (halves), pad 8 -> conflict-free ldmatrix
constexpr int BS = 24;    // sB1 row stride (halves): 16 data + 8 pad
constexpr int VS = 392;   // sV row stride (halves)

constexpr int SQ_BYTES = 128 * QS * 2;              // 100352
constexpr int SB_BYTES = 2 * N * BS * 2;            // 36864 (union with sV: 2*16*VS*2=25088)
constexpr int SROW_BYTES = 256 * 4;                 // 1024
constexpr int SMEM_TOTAL = SQ_BYTES + SB_BYTES + SROW_BYTES;  // 138240

__device__ __align__(16) __nv_bfloat16 g_v1[N * N];   // v1[n][k], bf16
__device__ float g_colsum[N * N];                     // colsum[i][c] = sum_n x2[i][n][c]

// ---------------------------------------------------------------------------
__device__ __forceinline__ uint32_t smem_u32(const void* p) {
    uint32_t a;
    asm("{ .reg .u64 t; cvta.to.shared.u64 t, %1; cvt.u32.u64 %0, t; }" : "=r"(a) : "l"(p));
    return a;
}
__device__ __forceinline__ void ldm4(uint32_t* r, uint32_t addr) {
    asm volatile("ldmatrix.sync.aligned.m8n8.x4.shared.b16 {%0,%1,%2,%3},[%4];"
                 : "=r"(r[0]), "=r"(r[1]), "=r"(r[2]), "=r"(r[3]) : "r"(addr));
}
__device__ __forceinline__ void ldm4t(uint32_t* r, uint32_t addr) {
    asm volatile("ldmatrix.sync.aligned.m8n8.x4.trans.shared.b16 {%0,%1,%2,%3},[%4];"
                 : "=r"(r[0]), "=r"(r[1]), "=r"(r[2]), "=r"(r[3]) : "r"(addr));
}
__device__ __forceinline__ void mma16816(float* d, const uint32_t* a, uint32_t b0, uint32_t b1) {
    asm volatile("mma.sync.aligned.m16n8k16.row.col.f32.bf16.bf16.f32 "
                 "{%0,%1,%2,%3},{%4,%5,%6,%7},{%8,%9},{%0,%1,%2,%3};"
                 : "+f"(d[0]), "+f"(d[1]), "+f"(d[2]), "+f"(d[3])
                 : "r"(a[0]), "r"(a[1]), "r"(a[2]), "r"(a[3]), "r"(b0), "r"(b1));
}
__device__ __forceinline__ uint32_t bf2_pack(float a, float b) {
    __nv_bfloat162 h = __floats2bfloat162_rn(a, b);
    return *reinterpret_cast<uint32_t*>(&h);
}

// ---------------------------------------------------------------------------
// v1[n][k] = sum_m x1[n][m]*W[k][m] + b[k]   (bf16 output)
// ---------------------------------------------------------------------------
__global__ void linear_kernel(const float* __restrict__ x1,
                              const float* __restrict__ W,
                              const float* __restrict__ b) {
    __shared__ float sW[16][17];
    __shared__ float sX[16][17];
    const int tx = threadIdx.x, ty = threadIdx.y;
    const int k = blockIdx.y * 16 + ty;
    const int n = blockIdx.x * 16 + tx;
    float acc = 0.0f;
    for (int m0 = 0; m0 < N; m0 += 16) {
        sW[ty][tx] = W[k * N + m0 + tx];
        sX[ty][tx] = x1[(blockIdx.x * 16 + ty) * N + m0 + tx];
        __syncthreads();
#pragma unroll
        for (int mm = 0; mm < 16; ++mm) acc += sW[ty][mm] * sX[tx][mm];
        __syncthreads();
    }
    g_v1[n * N + k] = __float2bfloat16(acc + b[k]);
}

// ---------------------------------------------------------------------------
// colsum[i][c] = sum_n x2[i][n][c]  (fp32)
// ---------------------------------------------------------------------------
__global__ void colsum_kernel(const float* __restrict__ x2) {
    const int i = blockIdx.x;
    const int c = threadIdx.x;
    const float* p = x2 + (size_t)i * N * N + c;
    float s = 0.0f;
#pragma unroll 8
    for (int n = 0; n < N; ++n) s += p[(size_t)n * N];
    g_colsum[i * N + c] = s;
}

// ---------------------------------------------------------------------------
// Fused attention: CTA = (128 q-rows, batch i). 8 warps = 4 (rows) x 2 (cols).
// ---------------------------------------------------------------------------
__global__ __launch_bounds__(256, 1)
void attn_kernel(const float* __restrict__ x2, float* __restrict__ out) {
    extern __shared__ char smem[];
    __nv_bfloat16* sQ = reinterpret_cast<__nv_bfloat16*>(smem);
    __nv_bfloat16* sB = reinterpret_cast<__nv_bfloat16*>(smem + SQ_BYTES);
    float* srow = reinterpret_cast<float*>(smem + SQ_BYTES + SB_BYTES);

    const int tid = threadIdx.x;
    const int lane = tid & 31;
    const int warp = tid >> 5;
    const int wr = warp & 3;      // row group: rows wr*32..+32
    const int wc = warp >> 2;     // col group: cols wc*192..+192
    const int i = blockIdx.y;
    const int j0 = blockIdx.x * 128;

    const uint32_t sQu = smem_u32(sQ);
    const uint32_t sBu = smem_u32(sB);

    // ldmatrix lane geometry
    const int rowA = (lane & 7) + ((lane >> 3) & 1) * 8;   // A tiles (non-trans)
    const int colA = (lane >> 4) * 8;
    const uint32_t aBase = sQu + ((wr * 32 + rowA) * QS + colA) * 2;

    const int rowB = (lane & 7) + ((lane >> 4) & 1) * 8;   // B1 tiles (non-trans)
    const int colB = ((lane >> 3) & 1) * 8;
    const uint32_t bBase1 = sBu + (rowB * BS + colB) * 2;

    const int rowV = (lane & 7) + ((lane >> 3) & 1) * 8;   // B2 tiles (trans)
    const int colV = ((lane >> 4) & 1) * 8;
    const uint32_t bBase2 = sBu + (rowV * VS + colV) * 2;

    // ---- stage Q (fp32 -> bf16) into sQ ----
    const float* Qg = x2 + ((size_t)i * N + j0) * N;
#pragma unroll
    for (int q = 0; q < 48; ++q) {
        int idx = tid + q * 256;            // 0..12287
        int row = idx / 96, c4 = idx % 96;
        float4 f = __ldg(reinterpret_cast<const float4*>(Qg + (size_t)row * N) + c4);
        uint2 u = make_uint2(bf2_pack(f.x, f.y), bf2_pack(f.z, f.w));
        *reinterpret_cast<uint2*>(sQ + row * QS + c4 * 4) = u;
    }

    float acc[2][24][4];
#pragma unroll
    for (int ma = 0; ma < 2; ++ma)
#pragma unroll
        for (int na = 0; na < 24; ++na)
#pragma unroll
            for (int r = 0; r < 4; ++r) acc[ma][na][r] = 0.0f;

    // =======================================================================
    // GEMM1: S = Q @ v1^T ; loop over k in chunks of 16, B chunk = v1[:, k16]
    // =======================================================================
    uint4 pre[3];
#pragma unroll
    for (int q = 0; q < 3; ++q) {                  // prefetch chunk 0
        int idx = tid + q * 256;                   // 0..767
        int row = idx >> 1, part = idx & 1;
        pre[q] = *reinterpret_cast<const uint4*>(g_v1 + row * N + part * 8);
    }

    for (int kc = 0; kc < 24; ++kc) {
        const int buf = kc & 1;
        __nv_bfloat16* sb = sB + buf * N * BS;
#pragma unroll
        for (int q = 0; q < 3; ++q) {
            int idx = tid + q * 256;
            int row = idx >> 1, part = idx & 1;
            *reinterpret_cast<uint4*>(sb + row * BS + part * 8) = pre[q];
        }
        __syncthreads();
        if (kc < 23) {
#pragma unroll
            for (int q = 0; q < 3; ++q) {
                int idx = tid + q * 256;
                int row = idx >> 1, part = idx & 1;
                pre[q] = *reinterpret_cast<const uint4*>(g_v1 + row * N + (kc + 1) * 16 + part * 8);
            }
        }
        uint32_t a[2][4];
#pragma unroll
        for (int ma = 0; ma < 2; ++ma)
            ldm4(a[ma], aBase + (ma * 16 * QS + kc * 16) * 2);
#pragma unroll
        for (int nbx = 0; nbx < 12; ++nbx) {
            uint32_t b[4];
            ldm4(b, bBase1 + (buf * N * BS + (wc * 192 + nbx * 16) * BS) * 2);
#pragma unroll
            for (int ma = 0; ma < 2; ++ma) {
                mma16816(acc[ma][2 * nbx], a[ma], b[0], b[1]);
                mma16816(acc[ma][2 * nbx + 1], a[ma], b[2], b[3]);
            }
        }
    }

    // =======================================================================
    // Softmax (no max-sub needed: |S/1000| < 0.1):  e = exp(z); delta = e/s - 1/N
    // =======================================================================
    float rs[2][2] = {{0.f, 0.f}, {0.f, 0.f}};
#pragma unroll
    for (int ma = 0; ma < 2; ++ma)
#pragma unroll
        for (int na = 0; na < 24; ++na) {
            float* d = acc[ma][na];
            d[0] = __expf(d[0] * SCALE_INV);
            d[1] = __expf(d[1] * SCALE_INV);
            d[2] = __expf(d[2] * SCALE_INV);
            d[3] = __expf(d[3] * SCALE_INV);
            rs[ma][0] += d[0] + d[1];
            rs[ma][1] += d[2] + d[3];
        }
#pragma unroll
    for (int ma = 0; ma < 2; ++ma)
#pragma unroll
        for (int h = 0; h < 2; ++h) {
            rs[ma][h] += __shfl_xor_sync(0xffffffffu, rs[ma][h], 1);
            rs[ma][h] += __shfl_xor_sync(0xffffffffu, rs[ma][h], 2);
        }
    if ((lane & 3) == 0) {
#pragma unroll
        for (int ma = 0; ma < 2; ++ma)
#pragma unroll
            for (int h = 0; h < 2; ++h)
                srow[wc * 128 + wr * 32 + ma * 16 + h * 8 + (lane >> 2)] = rs[ma][h];
    }
    __syncthreads();
    float invs[2][2];
#pragma unroll
    for (int ma = 0; ma < 2; ++ma)
#pragma unroll
        for (int h = 0; h < 2; ++h) {
            int r = wr * 32 + ma * 16 + h * 8 + (lane >> 2);
            invs[ma][h] = 1.0f / (srow[r] + srow[128 + r]);
        }

    // delta (bf16) overwrites sQ (Q is dead)
#pragma unroll
    for (int ma = 0; ma < 2; ++ma)
#pragma unroll
        for (int na = 0; na < 24; ++na) {
            int r = wr * 32 + ma * 16 + (lane >> 2);
            int c = wc * 192 + (na >> 1) * 16 + (na & 1) * 8 + (lane & 3) * 2;
            float* d = acc[ma][na];
            *reinterpret_cast<uint32_t*>(sQ + r * QS + c) =
                bf2_pack(d[0] * invs[ma][0] - INV_N, d[1] * invs[ma][0] - INV_N);
            *reinterpret_cast<uint32_t*>(sQ + (r + 8) * QS + c) =
                bf2_pack(d[2] * invs[ma][1] - INV_N, d[3] * invs[ma][1] - INV_N);
        }

    // =======================================================================
    // GEMM2: out_corr = delta @ V ; V chunks = x2[i][n16][:] fp32->bf16
    // =======================================================================
#pragma unroll
    for (int ma = 0; ma < 2; ++ma)
#pragma unroll
        for (int na = 0; na < 24; ++na)
#pragma unroll
            for (int r = 0; r < 4; ++r) acc[ma][na][r] = 0.0f;

    const float* Vg = x2 + (size_t)i * N * N;
    float4 vpre[6];
#pragma unroll
    for (int q = 0; q < 6; ++q) {                  // prefetch chunk 0
        int idx = tid + q * 256;                   // 0..1535
        int row = idx / 96, c4 = idx % 96;
        vpre[q] = __ldg(reinterpret_cast<const float4*>(Vg + (size_t)row * N) + c4);
    }

    for (int nc = 0; nc < 24; ++nc) {
        const int buf = nc & 1;
        __nv_bfloat16* sv = sB + buf * 16 * VS;
#pragma unroll
        for (int q = 0; q < 6; ++q) {
            int idx = tid + q * 256;
            int row = idx / 96, c4 = idx % 96;
            uint2 u = make_uint2(bf2_pack(vpre[q].x, vpre[q].y), bf2_pack(vpre[q].z, vpre[q].w));
            *reinterpret_cast<uint2*>(sv + row * VS + c4 * 4) = u;
        }
        __syncthreads();
        if (nc < 23) {
#pragma unroll
            for (int q = 0; q < 6; ++q) {
                int idx = tid + q * 256;
                int row = idx / 96, c4 = idx % 96;
                vpre[q] = __ldg(reinterpret_cast<const float4*>(
                              Vg + ((size_t)(nc + 1) * 16 + row) * N) + c4);
            }
        }
        uint32_t a[2][4];
#pragma unroll
        for (int ma = 0; ma < 2; ++ma)
            ldm4(a[ma], aBase + (ma * 16 * QS + nc * 16) * 2);
#pragma unroll
        for (int nbx = 0; nbx < 12; ++nbx) {
            uint32_t b[4];
            ldm4t(b, bBase2 + (buf * 16 * VS + wc * 192 + nbx * 16) * 2);
#pragma unroll
            for (int ma = 0; ma < 2; ++ma) {
                mma16816(acc[ma][2 * nbx], a[ma], b[0], b[1]);
                mma16816(acc[ma][2 * nbx + 1], a[ma], b[2], b[3]);
            }
        }
    }

    // ---- epilogue: out = acc + colsum/384 ----
    const float* cs = g_colsum + (size_t)i * N;
#pragma unroll
    for (int ma = 0; ma < 2; ++ma)
#pragma unroll
        for (int nbx = 0; nbx < 12; ++nbx)
#pragma unroll
            for (int ct = 0; ct < 2; ++ct) {
                int na = nbx * 2 + ct;
                int r = j0 + wr * 32 + ma * 16 + (lane >> 2);
                int c = wc * 192 + nbx * 16 + ct * 8 + (lane & 3) * 2;
                float cs0 = __ldg(cs + c) * INV_N;
                float cs1 = __ldg(cs + c + 1) * INV_N;
                float* d = acc[ma][na];
                float2 o0 = make_float2(d[0] + cs0, d[1] + cs1);
                float2 o1 = make_float2(d[2] + cs0, d[3] + cs1);
                *reinterpret_cast<float2*>(out + ((size_t)i * N + r) * N + c) = o0;
                *reinterpret_cast<float2*>(out + ((size_t)i * N + r + 8) * N + c) = o1;
            }
}

// ---------------------------------------------------------------------------
extern "C" void kernel_launch(void* const* d_in, const int* in_sizes, int n_in,
                              void* d_out, int out_size) {
    const float* x1 = (const float*)d_in[0];
    const float* x2 = (const float*)d_in[1];
    const float* W  = (const float*)d_in[2];
    const float* b  = (const float*)d_in[3];
    float* out = (float*)d_out;
    (void)in_sizes; (void)n_in; (void)out_size;

    {
        dim3 grid(N / 16, N / 16), block(16, 16);
        linear_kernel<<<grid, block>>>(x1, W, b);
    }
    colsum_kernel<<<N, N>>>(x2);
    {
        cudaFuncSetAttribute(attn_kernel, cudaFuncAttributeMaxDynamicSharedMemorySize, SMEM_TOTAL);
        dim3 grid(N / 128, N);
        attn_kernel<<<grid, 256, SMEM_TOTAL>>>(x2, out);
    }
}

// round 7
// speedup vs baseline: 1.1709x; 1.1709x over previous
#include <cuda_runtime.h>
#include <cuda_bf16.h>
#include <cstdint>

// out[i] = softmax((x2[i] @ v1^T)/1000) @ x2[i],  v1 = x1@W.T + b,  N=384.
// P = 1/384 + delta  ->  out = colsum(x2[i])/384 + delta @ x2[i].
// GEMMs: legacy mma.sync m16n8k16 bf16 (tcgen05 unavailable: harness targets compute_103).
// Kernel A (fused): 12 blocks compute v1 (bf16), 2304 blocks convert x2->bf16 + partial colsums.
// Kernel B: fused attention, cp.async triple-buffered staging of prebaked bf16 operands.

constexpr int N = 384;
constexpr float SCALE_INV = 1.0f / 1000.0f;
constexpr float INV_N = 1.0f / 384.0f;

constexpr int QS = 392;   // sQ row stride (halves): 384 + 8 pad
constexpr int BS = 24;    // GEMM1 B row stride (halves): 16 + 8 pad
constexpr int VS = 392;   // GEMM2 B row stride (halves)

constexpr int SQ_BYTES = 128 * QS * 2;        // 100352
constexpr int BUF_B    = 18432;               // max(384*BS*2, 16*VS*2) = max(18432,12544)
constexpr int OFF_BUF  = SQ_BYTES;
constexpr int OFF_SROW = OFF_BUF + 3 * BUF_B;            // 155648
constexpr int OFF_CS   = OFF_SROW + 256 * 4;             // 156672
constexpr int SMEM_ATTN = OFF_CS + 384 * 4;              // 158208

__device__ __align__(16) __nv_bfloat16 g_v1b[N * N];                 // v1[n][k] bf16
__device__ __align__(16) __nv_bfloat16 g_x2b[(size_t)N * N * N];     // x2 bf16 image
__device__ float g_cs6[(size_t)N * 6 * N];                           // partial colsums

// ---------------------------------------------------------------------------
__device__ __forceinline__ uint32_t smem_u32(const void* p) {
    uint32_t a;
    asm("{ .reg .u64 t; cvta.to.shared.u64 t, %1; cvt.u32.u64 %0, t; }" : "=r"(a) : "l"(p));
    return a;
}
__device__ __forceinline__ void ldm4(uint32_t* r, uint32_t addr) {
    asm volatile("ldmatrix.sync.aligned.m8n8.x4.shared.b16 {%0,%1,%2,%3},[%4];"
                 : "=r"(r[0]), "=r"(r[1]), "=r"(r[2]), "=r"(r[3]) : "r"(addr));
}
__device__ __forceinline__ void ldm4t(uint32_t* r, uint32_t addr) {
    asm volatile("ldmatrix.sync.aligned.m8n8.x4.trans.shared.b16 {%0,%1,%2,%3},[%4];"
                 : "=r"(r[0]), "=r"(r[1]), "=r"(r[2]), "=r"(r[3]) : "r"(addr));
}
__device__ __forceinline__ void mma16816(float* d, const uint32_t* a, uint32_t b0, uint32_t b1) {
    asm volatile("mma.sync.aligned.m16n8k16.row.col.f32.bf16.bf16.f32 "
                 "{%0,%1,%2,%3},{%4,%5,%6,%7},{%8,%9},{%0,%1,%2,%3};"
                 : "+f"(d[0]), "+f"(d[1]), "+f"(d[2]), "+f"(d[3])
                 : "r"(a[0]), "r"(a[1]), "r"(a[2]), "r"(a[3]), "r"(b0), "r"(b1));
}
__device__ __forceinline__ uint32_t bf2_pack(float a, float b) {
    __nv_bfloat162 h = __floats2bfloat162_rn(a, b);
    return *reinterpret_cast<uint32_t*>(&h);
}
__device__ __forceinline__ void cp16(uint32_t dst, const void* src) {
    asm volatile("cp.async.cg.shared.global [%0], [%1], 16;" :: "r"(dst), "l"(src));
}
#define CP_COMMIT() asm volatile("cp.async.commit_group;" ::: "memory")
#define CP_WAIT1()  asm volatile("cp.async.wait_group 1;" ::: "memory")

// ---------------------------------------------------------------------------
// prep kernel, grid (6, 386):
//   by in {0,1}: linear slab L = by*6+bx (32 n-rows of v1)
//   by >= 2:     convert+colsum for batch by-2, slab bx (64 rows of x2)
// ---------------------------------------------------------------------------
__global__ __launch_bounds__(256) void prep_kernel(const float* __restrict__ x1,
                                                   const float* __restrict__ W,
                                                   const float* __restrict__ b,
                                                   const float* __restrict__ x2) {
    extern __shared__ float dsf[];
    const int tid = threadIdx.x;
    const int bx = blockIdx.x, by = blockIdx.y;

    if (by < 2) {
        // ---------------- linear: v1[n][k] = sum_m x1[n][m]*W[k][m] + b[k] --------
        float* sX = dsf;                // [32][17]
        float* sW = dsf + 32 * 17;      // [384][17]
        const int L = by * 6 + bx;
        const int n0 = L * 32;
        const int nl = (tid & 15) * 2;       // local n pair
        const int k0 = (tid >> 4) * 24;      // 16 k-groups of 24
        float acc[2][24];
#pragma unroll
        for (int r = 0; r < 2; ++r)
#pragma unroll
            for (int j = 0; j < 24; ++j) acc[r][j] = 0.0f;

        for (int m0 = 0; m0 < N; m0 += 16) {
#pragma unroll
            for (int q = 0; q < 2; ++q) {
                int idx = tid + q * 256;     // 512 = 32*16
                int n = idx >> 4, m = idx & 15;
                sX[n * 17 + m] = x1[(size_t)(n0 + n) * N + m0 + m];
            }
#pragma unroll
            for (int q = 0; q < 24; ++q) {
                int idx = tid + q * 256;     // 6144 = 384*16
                int k = idx >> 4, m = idx & 15;
                sW[k * 17 + m] = W[(size_t)k * N + m0 + m];
            }
            __syncthreads();
#pragma unroll
            for (int mm = 0; mm < 16; ++mm) {
                float x0 = sX[nl * 17 + mm];
                float x1v = sX[(nl + 1) * 17 + mm];
#pragma unroll
                for (int j = 0; j < 24; ++j) {
                    float w = sW[(k0 + j) * 17 + mm];
                    acc[0][j] += x0 * w;
                    acc[1][j] += x1v * w;
                }
            }
            __syncthreads();
        }
#pragma unroll
        for (int r = 0; r < 2; ++r) {
            int n = n0 + nl + r;
            uint32_t* dst = reinterpret_cast<uint32_t*>(g_v1b + (size_t)n * N + k0);
#pragma unroll
            for (int j = 0; j < 12; ++j)
                dst[j] = bf2_pack(acc[r][2 * j] + __ldg(b + k0 + 2 * j),
                                  acc[r][2 * j + 1] + __ldg(b + k0 + 2 * j + 1));
        }
        return;
    }

    // ---------------- x2 -> bf16 image + partial colsum ----------------------
    float* st = dsf;                     // [64][388]
    const int i = by - 2, s = bx;
    const float* src = x2 + ((size_t)i * N + s * 64) * N;
#pragma unroll
    for (int q = 0; q < 24; ++q) {
        int idx = tid + q * 256;          // 6144 = 64*96
        int row = idx / 96, c4 = idx % 96;
        float4 f = __ldg(reinterpret_cast<const float4*>(src + (size_t)row * N) + c4);
        *reinterpret_cast<float4*>(st + row * 388 + c4 * 4) = f;
    }
    __syncthreads();
    // colsum over the 64 rows
    {
        float s0 = 0.f, s1 = 0.f;
#pragma unroll 8
        for (int r = 0; r < 64; ++r) {
            s0 += st[r * 388 + tid];
            if (tid < 128) s1 += st[r * 388 + 256 + tid];
        }
        g_cs6[((size_t)i * 6 + s) * N + tid] = s0;
        if (tid < 128) g_cs6[((size_t)i * 6 + s) * N + 256 + tid] = s1;
    }
    // bf16 image (row-major, same indexing as x2)
    __nv_bfloat16* dst = g_x2b + ((size_t)i * N + s * 64) * N;
#pragma unroll
    for (int q = 0; q < 24; ++q) {
        int idx = tid + q * 256;
        int row = idx / 96, c4 = idx % 96;
        float4 f = *reinterpret_cast<const float4*>(st + row * 388 + c4 * 4);
        uint2 u = make_uint2(bf2_pack(f.x, f.y), bf2_pack(f.z, f.w));
        *reinterpret_cast<uint2*>(dst + (size_t)row * N + c4 * 4) = u;
    }
}

// ---------------------------------------------------------------------------
// Fused attention: CTA = (128 q-rows, batch). 8 warps = 4 (rows) x 2 (cols).
// cp.async triple-buffered staging; operands prebaked bf16.
// ---------------------------------------------------------------------------
__global__ __launch_bounds__(256, 1)
void attn_kernel(float* __restrict__ out) {
    extern __shared__ char smem[];
    __nv_bfloat16* sQ = reinterpret_cast<__nv_bfloat16*>(smem);
    float* srow = reinterpret_cast<float*>(smem + OFF_SROW);
    float* cs_s = reinterpret_cast<float*>(smem + OFF_CS);

    const int tid = threadIdx.x;
    const int lane = tid & 31;
    const int warp = tid >> 5;
    const int wr = warp & 3;
    const int wc = warp >> 2;
    const int i = blockIdx.y;
    const int j0 = blockIdx.x * 128;

    const uint32_t sQu = smem_u32(smem);
    const uint32_t sBu = sQu + OFF_BUF;

    // ldmatrix lane geometry (as validated in R4)
    const int rowA = (lane & 7) + ((lane >> 3) & 1) * 8;
    const int colA = (lane >> 4) * 8;
    const uint32_t aBase = sQu + ((wr * 32 + rowA) * QS + colA) * 2;

    const int rowB = (lane & 7) + ((lane >> 4) & 1) * 8;
    const int colB = ((lane >> 3) & 1) * 8;
    const uint32_t bBase1 = sBu + (rowB * BS + colB) * 2;

    const int rowV = (lane & 7) + ((lane >> 3) & 1) * 8;
    const int colV = ((lane >> 4) & 1) * 8;
    const uint32_t bBase2 = sBu + (rowV * VS + colV) * 2;

    // ---- stage Q (bf16 image, contiguous 96KB) + v1 chunk0 : group 0 ----
    const char* qsrc = reinterpret_cast<const char*>(g_x2b + ((size_t)i * N + j0) * N);
#pragma unroll
    for (int q = 0; q < 24; ++q) {
        int idx = tid + q * 256;           // 6144 transfers of 16B
        int row = idx / 48, c = idx % 48;
        cp16(sQu + row * 784 + c * 16, qsrc + (size_t)idx * 16);
    }
    const char* v1src = reinterpret_cast<const char*>(g_v1b);
#pragma unroll
    for (int q = 0; q < 3; ++q) {          // chunk 0 -> buf0
        int idx = tid + q * 256;           // 768 = 384*2
        int n = idx >> 1, h = idx & 1;
        cp16(sBu + n * 48 + h * 16, v1src + (size_t)n * 768 + h * 16);
    }
    CP_COMMIT();
#pragma unroll
    for (int q = 0; q < 3; ++q) {          // chunk 1 -> buf1
        int idx = tid + q * 256;
        int n = idx >> 1, h = idx & 1;
        cp16(sBu + BUF_B + n * 48 + h * 16, v1src + (size_t)n * 768 + 32 + h * 16);
    }
    CP_COMMIT();

    float acc[2][24][4];
#pragma unroll
    for (int ma = 0; ma < 2; ++ma)
#pragma unroll
        for (int na = 0; na < 24; ++na)
#pragma unroll
            for (int r = 0; r < 4; ++r) acc[ma][na][r] = 0.0f;

    // =================== GEMM1: S = Q @ v1^T ===================
    for (int kc = 0; kc < 24; ++kc) {
        const int buf = kc % 3;
        CP_WAIT1();
        __syncthreads();
        if (kc + 2 < 24) {
            const int nb = (kc + 2) % 3;
#pragma unroll
            for (int q = 0; q < 3; ++q) {
                int idx = tid + q * 256;
                int n = idx >> 1, h = idx & 1;
                cp16(sBu + nb * BUF_B + n * 48 + h * 16,
                     v1src + (size_t)n * 768 + (kc + 2) * 32 + h * 16);
            }
        }
        CP_COMMIT();
        uint32_t a[2][4];
#pragma unroll
        for (int ma = 0; ma < 2; ++ma)
            ldm4(a[ma], aBase + (ma * 16 * QS + kc * 16) * 2);
#pragma unroll
        for (int nbx = 0; nbx < 12; ++nbx) {
            uint32_t bfr[4];
            ldm4(bfr, bBase1 + buf * BUF_B + (wc * 192 + nbx * 16) * 48);
#pragma unroll
            for (int ma = 0; ma < 2; ++ma) {
                mma16816(acc[ma][2 * nbx], a[ma], bfr[0], bfr[1]);
                mma16816(acc[ma][2 * nbx + 1], a[ma], bfr[2], bfr[3]);
            }
        }
    }

    // ---- prefetch V chunks 0,1 (overlap with softmax) ----
    const char* vsrc = reinterpret_cast<const char*>(g_x2b + (size_t)i * N * N);
#pragma unroll
    for (int q = 0; q < 3; ++q) {          // V chunk 0 -> buf0 (16 rows x 768B contiguous)
        int idx = tid + q * 256;
        int row = idx / 48, c = idx % 48;
        cp16(sBu + row * 784 + c * 16, vsrc + (size_t)idx * 16);
    }
    CP_COMMIT();
#pragma unroll
    for (int q = 0; q < 3; ++q) {          // V chunk 1 -> buf1
        int idx = tid + q * 256;
        int row = idx / 48, c = idx % 48;
        cp16(sBu + BUF_B + row * 784 + c * 16, vsrc + 12288 + (size_t)idx * 16);
    }
    CP_COMMIT();

    // ---- colsum -> smem ----
    {
        float s0 = 0.f;
#pragma unroll
        for (int p = 0; p < 6; ++p) s0 += __ldg(g_cs6 + ((size_t)i * 6 + p) * N + tid);
        cs_s[tid] = s0;
        if (tid < 128) {
            float s1 = 0.f;
#pragma unroll
            for (int p = 0; p < 6; ++p) s1 += __ldg(g_cs6 + ((size_t)i * 6 + p) * N + 256 + tid);
            cs_s[256 + tid] = s1;
        }
    }

    // =================== softmax: delta = e/s - 1/N (bf16 into sQ) ===================
    float rs[2][2] = {{0.f, 0.f}, {0.f, 0.f}};
#pragma unroll
    for (int ma = 0; ma < 2; ++ma)
#pragma unroll
        for (int na = 0; na < 24; ++na) {
            float* d = acc[ma][na];
            d[0] = __expf(d[0] * SCALE_INV);
            d[1] = __expf(d[1] * SCALE_INV);
            d[2] = __expf(d[2] * SCALE_INV);
            d[3] = __expf(d[3] * SCALE_INV);
            rs[ma][0] += d[0] + d[1];
            rs[ma][1] += d[2] + d[3];
        }
#pragma unroll
    for (int ma = 0; ma < 2; ++ma)
#pragma unroll
        for (int h = 0; h < 2; ++h) {
            rs[ma][h] += __shfl_xor_sync(0xffffffffu, rs[ma][h], 1);
            rs[ma][h] += __shfl_xor_sync(0xffffffffu, rs[ma][h], 2);
        }
    if ((lane & 3) == 0) {
#pragma unroll
        for (int ma = 0; ma < 2; ++ma)
#pragma unroll
            for (int h = 0; h < 2; ++h)
                srow[wc * 128 + wr * 32 + ma * 16 + h * 8 + (lane >> 2)] = rs[ma][h];
    }
    __syncthreads();
    float invs[2][2];
#pragma unroll
    for (int ma = 0; ma < 2; ++ma)
#pragma unroll
        for (int h = 0; h < 2; ++h) {
            int r = wr * 32 + ma * 16 + h * 8 + (lane >> 2);
            invs[ma][h] = 1.0f / (srow[r] + srow[128 + r]);
        }
#pragma unroll
    for (int ma = 0; ma < 2; ++ma)
#pragma unroll
        for (int na = 0; na < 24; ++na) {
            int r = wr * 32 + ma * 16 + (lane >> 2);
            int c = wc * 192 + (na >> 1) * 16 + (na & 1) * 8 + (lane & 3) * 2;
            float* d = acc[ma][na];
            *reinterpret_cast<uint32_t*>(sQ + r * QS + c) =
                bf2_pack(d[0] * invs[ma][0] - INV_N, d[1] * invs[ma][0] - INV_N);
            *reinterpret_cast<uint32_t*>(sQ + (r + 8) * QS + c) =
                bf2_pack(d[2] * invs[ma][1] - INV_N, d[3] * invs[ma][1] - INV_N);
        }
    __syncthreads();

    // =================== GEMM2: corr = delta @ V ===================
#pragma unroll
    for (int ma = 0; ma < 2; ++ma)
#pragma unroll
        for (int na = 0; na < 24; ++na)
#pragma unroll
            for (int r = 0; r < 4; ++r) acc[ma][na][r] = 0.0f;

    for (int nc = 0; nc < 24; ++nc) {
        const int buf = nc % 3;
        CP_WAIT1();
        __syncthreads();
        if (nc + 2 < 24) {
            const int nb = (nc + 2) % 3;
#pragma unroll
            for (int q = 0; q < 3; ++q) {
                int idx = tid + q * 256;
                int row = idx / 48, c = idx % 48;
                cp16(sBu + nb * BUF_B + row * 784 + c * 16,
                     vsrc + (size_t)(nc + 2) * 12288 + (size_t)idx * 16);
            }
        }
        CP_COMMIT();
        uint32_t a[2][4];
#pragma unroll
        for (int ma = 0; ma < 2; ++ma)
            ldm4(a[ma], aBase + (ma * 16 * QS + nc * 16) * 2);
#pragma unroll
        for (int nbx = 0; nbx < 12; ++nbx) {
            uint32_t bfr[4];
            ldm4t(bfr, bBase2 + buf * BUF_B + (wc * 192 + nbx * 16) * 2);
#pragma unroll
            for (int ma = 0; ma < 2; ++ma) {
                mma16816(acc[ma][2 * nbx], a[ma], bfr[0], bfr[1]);
                mma16816(acc[ma][2 * nbx + 1], a[ma], bfr[2], bfr[3]);
            }
        }
    }

    // =================== epilogue: out = corr + colsum/384 ===================
#pragma unroll
    for (int ma = 0; ma < 2; ++ma)
#pragma unroll
        for (int nbx = 0; nbx < 12; ++nbx)
#pragma unroll
            for (int ct = 0; ct < 2; ++ct) {
                int na = nbx * 2 + ct;
                int r = j0 + wr * 32 + ma * 16 + (lane >> 2);
                int c = wc * 192 + nbx * 16 + ct * 8 + (lane & 3) * 2;
                float cs0 = cs_s[c] * INV_N;
                float cs1 = cs_s[c + 1] * INV_N;
                float* d = acc[ma][na];
                float2 o0 = make_float2(d[0] + cs0, d[1] + cs1);
                float2 o1 = make_float2(d[2] + cs0, d[3] + cs1);
                *reinterpret_cast<float2*>(out + ((size_t)i * N + r) * N + c) = o0;
                *reinterpret_cast<float2*>(out + ((size_t)i * N + r + 8) * N + c) = o1;
            }
}

// ---------------------------------------------------------------------------
extern "C" void kernel_launch(void* const* d_in, const int* in_sizes, int n_in,
                              void* d_out, int out_size) {
    const float* x1 = (const float*)d_in[0];
    const float* x2 = (const float*)d_in[1];
    const float* W  = (const float*)d_in[2];
    const float* b  = (const float*)d_in[3];
    float* out = (float*)d_out;
    (void)in_sizes; (void)n_in; (void)out_size;

    {
        constexpr int SMEM_PREP = 64 * 388 * 4;   // 99328 (covers linear's 28KB too)
        cudaFuncSetAttribute(prep_kernel, cudaFuncAttributeMaxDynamicSharedMemorySize, SMEM_PREP);
        dim3 g(6, 386);   // y=0,1: linear (12 blocks); y>=2: convert+colsum (2304 blocks)
        prep_kernel<<<g, 256, SMEM_PREP>>>(x1, W, b, x2);
    }
    {
        cudaFuncSetAttribute(attn_kernel, cudaFuncAttributeMaxDynamicSharedMemorySize, SMEM_ATTN);
        dim3 g(3, 384);
        attn_kernel<<<g, 256, SMEM_ATTN>>>(out);
    }
}

// round 8
// speedup vs baseline: 1.3857x; 1.1835x over previous
#include <cuda_runtime.h>
#include <cuda_bf16.h>
#include <cstdint>

// out[i] = softmax((x2[i] @ v1^T)/1000) @ x2[i],  v1 = x1@W.T + b,  N=384.
// P = 1/384 + delta  ->  out = colsum(x2[i])/384 + delta @ x2[i].
// GEMMs: mma.sync m16n8k16 bf16. Prep kernel prebakes bf16 operands + colsums.
// Attn: 512 threads, 16 warps (4 row-groups x 4 col-groups), 96 acc regs/warp.

constexpr int N = 384;
constexpr float SCALE_INV = 1.0f / 1000.0f;
constexpr float INV_N = 1.0f / 384.0f;

constexpr int QS = 392;   // sQ row stride (halves): 384 + 8 pad
constexpr int BS = 24;    // GEMM1 B row stride (halves): 16 + 8 pad
constexpr int VS = 392;   // GEMM2 B row stride (halves)

constexpr int SQ_BYTES = 128 * QS * 2;        // 100352
constexpr int BUF_B    = 18432;               // max(384*BS*2, 16*VS*2)
constexpr int OFF_BUF  = SQ_BYTES;
constexpr int OFF_SROW = OFF_BUF + 3 * BUF_B;            // 155648
constexpr int OFF_CS   = OFF_SROW + 512 * 4;             // 157696
constexpr int SMEM_ATTN = OFF_CS + 384 * 4;              // 159232

__device__ __align__(16) __nv_bfloat16 g_v1b[N * N];                 // v1[n][k] bf16
__device__ __align__(16) __nv_bfloat16 g_x2b[(size_t)N * N * N];     // x2 bf16 image
__device__ float g_cs6[(size_t)N * 6 * N];                           // partial colsums

// ---------------------------------------------------------------------------
__device__ __forceinline__ uint32_t smem_u32(const void* p) {
    uint32_t a;
    asm("{ .reg .u64 t; cvta.to.shared.u64 t, %1; cvt.u32.u64 %0, t; }" : "=r"(a) : "l"(p));
    return a;
}
__device__ __forceinline__ void ldm4(uint32_t* r, uint32_t addr) {
    asm volatile("ldmatrix.sync.aligned.m8n8.x4.shared.b16 {%0,%1,%2,%3},[%4];"
                 : "=r"(r[0]), "=r"(r[1]), "=r"(r[2]), "=r"(r[3]) : "r"(addr));
}
__device__ __forceinline__ void ldm4t(uint32_t* r, uint32_t addr) {
    asm volatile("ldmatrix.sync.aligned.m8n8.x4.trans.shared.b16 {%0,%1,%2,%3},[%4];"
                 : "=r"(r[0]), "=r"(r[1]), "=r"(r[2]), "=r"(r[3]) : "r"(addr));
}
__device__ __forceinline__ void mma16816(float* d, const uint32_t* a, uint32_t b0, uint32_t b1) {
    asm volatile("mma.sync.aligned.m16n8k16.row.col.f32.bf16.bf16.f32 "
                 "{%0,%1,%2,%3},{%4,%5,%6,%7},{%8,%9},{%0,%1,%2,%3};"
                 : "+f"(d[0]), "+f"(d[1]), "+f"(d[2]), "+f"(d[3])
                 : "r"(a[0]), "r"(a[1]), "r"(a[2]), "r"(a[3]), "r"(b0), "r"(b1));
}
__device__ __forceinline__ uint32_t bf2_pack(float a, float b) {
    __nv_bfloat162 h = __floats2bfloat162_rn(a, b);
    return *reinterpret_cast<uint32_t*>(&h);
}
__device__ __forceinline__ void cp16(uint32_t dst, const void* src) {
    asm volatile("cp.async.cg.shared.global [%0], [%1], 16;" :: "r"(dst), "l"(src));
}
#define CP_COMMIT() asm volatile("cp.async.commit_group;" ::: "memory")
#define CP_WAIT1()  asm volatile("cp.async.wait_group 1;" ::: "memory")

// ---------------------------------------------------------------------------
// prep kernel, grid (6, 386): by<2 -> linear slab; by>=2 -> x2 bf16 + colsum
// ---------------------------------------------------------------------------
__global__ __launch_bounds__(256) void prep_kernel(const float* __restrict__ x1,
                                                   const float* __restrict__ W,
                                                   const float* __restrict__ b,
                                                   const float* __restrict__ x2) {
    extern __shared__ float dsf[];
    const int tid = threadIdx.x;
    const int bx = blockIdx.x, by = blockIdx.y;

    if (by < 2) {
        float* sX = dsf;                // [32][17]
        float* sW = dsf + 32 * 17;      // [384][17]
        const int L = by * 6 + bx;
        const int n0 = L * 32;
        const int nl = (tid & 15) * 2;
        const int k0 = (tid >> 4) * 24;
        float acc[2][24];
#pragma unroll
        for (int r = 0; r < 2; ++r)
#pragma unroll
            for (int j = 0; j < 24; ++j) acc[r][j] = 0.0f;

        for (int m0 = 0; m0 < N; m0 += 16) {
#pragma unroll
            for (int q = 0; q < 2; ++q) {
                int idx = tid + q * 256;
                int n = idx >> 4, m = idx & 15;
                sX[n * 17 + m] = x1[(size_t)(n0 + n) * N + m0 + m];
            }
#pragma unroll
            for (int q = 0; q < 24; ++q) {
                int idx = tid + q * 256;
                int k = idx >> 4, m = idx & 15;
                sW[k * 17 + m] = W[(size_t)k * N + m0 + m];
            }
            __syncthreads();
#pragma unroll
            for (int mm = 0; mm < 16; ++mm) {
                float x0 = sX[nl * 17 + mm];
                float x1v = sX[(nl + 1) * 17 + mm];
#pragma unroll
                for (int j = 0; j < 24; ++j) {
                    float w = sW[(k0 + j) * 17 + mm];
                    acc[0][j] += x0 * w;
                    acc[1][j] += x1v * w;
                }
            }
            __syncthreads();
        }
#pragma unroll
        for (int r = 0; r < 2; ++r) {
            int n = n0 + nl + r;
            uint32_t* dst = reinterpret_cast<uint32_t*>(g_v1b + (size_t)n * N + k0);
#pragma unroll
            for (int j = 0; j < 12; ++j)
                dst[j] = bf2_pack(acc[r][2 * j] + __ldg(b + k0 + 2 * j),
                                  acc[r][2 * j + 1] + __ldg(b + k0 + 2 * j + 1));
        }
        return;
    }

    float* st = dsf;                     // [64][388]
    const int i = by - 2, s = bx;
    const float* src = x2 + ((size_t)i * N + s * 64) * N;
#pragma unroll
    for (int q = 0; q < 24; ++q) {
        int idx = tid + q * 256;
        int row = idx / 96, c4 = idx % 96;
        float4 f = __ldg(reinterpret_cast<const float4*>(src + (size_t)row * N) + c4);
        *reinterpret_cast<float4*>(st + row * 388 + c4 * 4) = f;
    }
    __syncthreads();
    {
        float s0 = 0.f, s1 = 0.f;
#pragma unroll 8
        for (int r = 0; r < 64; ++r) {
            s0 += st[r * 388 + tid];
            if (tid < 128) s1 += st[r * 388 + 256 + tid];
        }
        g_cs6[((size_t)i * 6 + s) * N + tid] = s0;
        if (tid < 128) g_cs6[((size_t)i * 6 + s) * N + 256 + tid] = s1;
    }
    __nv_bfloat16* dst = g_x2b + ((size_t)i * N + s * 64) * N;
#pragma unroll
    for (int q = 0; q < 24; ++q) {
        int idx = tid + q * 256;
        int row = idx / 96, c4 = idx % 96;
        float4 f = *reinterpret_cast<const float4*>(st + row * 388 + c4 * 4);
        uint2 u = make_uint2(bf2_pack(f.x, f.y), bf2_pack(f.z, f.w));
        *reinterpret_cast<uint2*>(dst + (size_t)row * N + c4 * 4) = u;
    }
}

// ---------------------------------------------------------------------------
// Fused attention: 512 threads, 16 warps = 4 row-groups x 4 col-groups.
// Each warp: 32 rows x 96 cols (2 m-tiles x 12 n8-tiles, 96 acc regs).
// ---------------------------------------------------------------------------
__global__ __launch_bounds__(512, 1)
void attn_kernel(float* __restrict__ out) {
    extern __shared__ char smem[];
    __nv_bfloat16* sQ = reinterpret_cast<__nv_bfloat16*>(smem);
    float* srow = reinterpret_cast<float*>(smem + OFF_SROW);   // [4 wc][128 rows]
    float* cs_s = reinterpret_cast<float*>(smem + OFF_CS);

    const int tid = threadIdx.x;
    const int lane = tid & 31;
    const int warp = tid >> 5;
    const int wr = warp & 3;       // rows wr*32..+32
    const int wc = warp >> 2;      // cols wc*96..+96
    const int i = blockIdx.y;
    const int j0 = blockIdx.x * 128;

    const uint32_t sQu = smem_u32(smem);
    const uint32_t sBu = sQu + OFF_BUF;

    const int rowA = (lane & 7) + ((lane >> 3) & 1) * 8;
    const int colA = (lane >> 4) * 8;
    const uint32_t aBase = sQu + ((wr * 32 + rowA) * QS + colA) * 2;

    const int rowB = (lane & 7) + ((lane >> 4) & 1) * 8;
    const int colB = ((lane >> 3) & 1) * 8;
    const uint32_t bBase1 = sBu + (rowB * BS + colB) * 2;

    const int rowV = (lane & 7) + ((lane >> 3) & 1) * 8;
    const int colV = ((lane >> 4) & 1) * 8;
    const uint32_t bBase2 = sBu + (rowV * VS + colV) * 2;

    // ---- stage Q (contiguous 96KB bf16) + v1 chunks 0,1 ----
    const char* qsrc = reinterpret_cast<const char*>(g_x2b + ((size_t)i * N + j0) * N);
#pragma unroll
    for (int q = 0; q < 12; ++q) {
        int idx = tid + q * 512;           // 6144 transfers of 16B
        int row = idx / 48, c = idx % 48;
        cp16(sQu + row * 784 + c * 16, qsrc + (size_t)idx * 16);
    }
    const char* v1src = reinterpret_cast<const char*>(g_v1b);
#pragma unroll
    for (int q = 0; q < 2; ++q) {          // chunk 0 -> buf0 (768 transfers)
        int idx = tid + q * 512;
        if (idx < 768) {
            int n = idx >> 1, h = idx & 1;
            cp16(sBu + n * 48 + h * 16, v1src + (size_t)n * 768 + h * 16);
        }
    }
    CP_COMMIT();
#pragma unroll
    for (int q = 0; q < 2; ++q) {          // chunk 1 -> buf1
        int idx = tid + q * 512;
        if (idx < 768) {
            int n = idx >> 1, h = idx & 1;
            cp16(sBu + BUF_B + n * 48 + h * 16, v1src + (size_t)n * 768 + 32 + h * 16);
        }
    }
    CP_COMMIT();

    float acc[2][12][4];
#pragma unroll
    for (int ma = 0; ma < 2; ++ma)
#pragma unroll
        for (int na = 0; na < 12; ++na)
#pragma unroll
            for (int r = 0; r < 4; ++r) acc[ma][na][r] = 0.0f;

    // =================== GEMM1: S = Q @ v1^T ===================
    for (int kc = 0; kc < 24; ++kc) {
        const int buf = kc % 3;
        CP_WAIT1();
        __syncthreads();
        if (kc + 2 < 24) {
            const int nb = (kc + 2) % 3;
#pragma unroll
            for (int q = 0; q < 2; ++q) {
                int idx = tid + q * 512;
                if (idx < 768) {
                    int n = idx >> 1, h = idx & 1;
                    cp16(sBu + nb * BUF_B + n * 48 + h * 16,
                         v1src + (size_t)n * 768 + (kc + 2) * 32 + h * 16);
                }
            }
        }
        CP_COMMIT();
        uint32_t a[2][4];
#pragma unroll
        for (int ma = 0; ma < 2; ++ma)
            ldm4(a[ma], aBase + (ma * 16 * QS + kc * 16) * 2);
#pragma unroll
        for (int nbx = 0; nbx < 6; ++nbx) {
            uint32_t bfr[4];
            ldm4(bfr, bBase1 + buf * BUF_B + (wc * 96 + nbx * 16) * 48);
#pragma unroll
            for (int ma = 0; ma < 2; ++ma) {
                mma16816(acc[ma][2 * nbx], a[ma], bfr[0], bfr[1]);
                mma16816(acc[ma][2 * nbx + 1], a[ma], bfr[2], bfr[3]);
            }
        }
    }

    // ---- prefetch V chunks 0,1 (overlap with softmax) ----
    const char* vsrc = reinterpret_cast<const char*>(g_x2b + (size_t)i * N * N);
#pragma unroll
    for (int q = 0; q < 2; ++q) {          // V chunk 0 -> buf0 (768 transfers)
        int idx = tid + q * 512;
        if (idx < 768) {
            int row = idx / 48, c = idx % 48;
            cp16(sBu + row * 784 + c * 16, vsrc + (size_t)idx * 16);
        }
    }
    CP_COMMIT();
#pragma unroll
    for (int q = 0; q < 2; ++q) {          // V chunk 1 -> buf1
        int idx = tid + q * 512;
        if (idx < 768) {
            int row = idx / 48, c = idx % 48;
            cp16(sBu + BUF_B + row * 784 + c * 16, vsrc + 12288 + (size_t)idx * 16);
        }
    }
    CP_COMMIT();

    // ---- colsum -> smem ----
    if (tid < 384) {
        float s0 = 0.f;
#pragma unroll
        for (int p = 0; p < 6; ++p) s0 += __ldg(g_cs6 + ((size_t)i * 6 + p) * N + tid);
        cs_s[tid] = s0;
    }

    // =================== softmax: delta = e/s - 1/N (bf16 into sQ) ===================
    float rs[2][2] = {{0.f, 0.f}, {0.f, 0.f}};
#pragma unroll
    for (int ma = 0; ma < 2; ++ma)
#pragma unroll
        for (int na = 0; na < 12; ++na) {
            float* d = acc[ma][na];
            d[0] = __expf(d[0] * SCALE_INV);
            d[1] = __expf(d[1] * SCALE_INV);
            d[2] = __expf(d[2] * SCALE_INV);
            d[3] = __expf(d[3] * SCALE_INV);
            rs[ma][0] += d[0] + d[1];
            rs[ma][1] += d[2] + d[3];
        }
#pragma unroll
    for (int ma = 0; ma < 2; ++ma)
#pragma unroll
        for (int h = 0; h < 2; ++h) {
            rs[ma][h] += __shfl_xor_sync(0xffffffffu, rs[ma][h], 1);
            rs[ma][h] += __shfl_xor_sync(0xffffffffu, rs[ma][h], 2);
        }
    if ((lane & 3) == 0) {
#pragma unroll
        for (int ma = 0; ma < 2; ++ma)
#pragma unroll
            for (int h = 0; h < 2; ++h)
                srow[wc * 128 + wr * 32 + ma * 16 + h * 8 + (lane >> 2)] = rs[ma][h];
    }
    __syncthreads();
    float invs[2][2];
#pragma unroll
    for (int ma = 0; ma < 2; ++ma)
#pragma unroll
        for (int h = 0; h < 2; ++h) {
            int r = wr * 32 + ma * 16 + h * 8 + (lane >> 2);
            invs[ma][h] = 1.0f / (srow[r] + srow[128 + r] + srow[256 + r] + srow[384 + r]);
        }
#pragma unroll
    for (int ma = 0; ma < 2; ++ma)
#pragma unroll
        for (int na = 0; na < 12; ++na) {
            int r = wr * 32 + ma * 16 + (lane >> 2);
            int c = wc * 96 + (na >> 1) * 16 + (na & 1) * 8 + (lane & 3) * 2;
            float* d = acc[ma][na];
            *reinterpret_cast<uint32_t*>(sQ + r * QS + c) =
                bf2_pack(d[0] * invs[ma][0] - INV_N, d[1] * invs[ma][0] - INV_N);
            *reinterpret_cast<uint32_t*>(sQ + (r + 8) * QS + c) =
                bf2_pack(d[2] * invs[ma][1] - INV_N, d[3] * invs[ma][1] - INV_N);
        }
    __syncthreads();

    // =================== GEMM2: corr = delta @ V ===================
#pragma unroll
    for (int ma = 0; ma < 2; ++ma)
#pragma unroll
        for (int na = 0; na < 12; ++na)
#pragma unroll
            for (int r = 0; r < 4; ++r) acc[ma][na][r] = 0.0f;

    for (int nc = 0; nc < 24; ++nc) {
        const int buf = nc % 3;
        CP_WAIT1();
        __syncthreads();
        if (nc + 2 < 24) {
            const int nb = (nc + 2) % 3;
#pragma unroll
            for (int q = 0; q < 2; ++q) {
                int idx = tid + q * 512;
                if (idx < 768) {
                    int row = idx / 48, c = idx % 48;
                    cp16(sBu + nb * BUF_B + row * 784 + c * 16,
                         vsrc + (size_t)(nc + 2) * 12288 + (size_t)idx * 16);
                }
            }
        }
        CP_COMMIT();
        uint32_t a[2][4];
#pragma unroll
        for (int ma = 0; ma < 2; ++ma)
            ldm4(a[ma], aBase + (ma * 16 * QS + nc * 16) * 2);
#pragma unroll
        for (int nbx = 0; nbx < 6; ++nbx) {
            uint32_t bfr[4];
            ldm4t(bfr, bBase2 + buf * BUF_B + (wc * 96 + nbx * 16) * 2);
#pragma unroll
            for (int ma = 0; ma < 2; ++ma) {
                mma16816(acc[ma][2 * nbx], a[ma], bfr[0], bfr[1]);
                mma16816(acc[ma][2 * nbx + 1], a[ma], bfr[2], bfr[3]);
            }
        }
    }

    // =================== epilogue: out = corr + colsum/384 ===================
#pragma unroll
    for (int ma = 0; ma < 2; ++ma)
#pragma unroll
        for (int nbx = 0; nbx < 6; ++nbx)
#pragma unroll
            for (int ct = 0; ct < 2; ++ct) {
                int na = nbx * 2 + ct;
                int r = j0 + wr * 32 + ma * 16 + (lane >> 2);
                int c = wc * 96 + nbx * 16 + ct * 8 + (lane & 3) * 2;
                float cs0 = cs_s[c] * INV_N;
                float cs1 = cs_s[c + 1] * INV_N;
                float* d = acc[ma][na];
                float2 o0 = make_float2(d[0] + cs0, d[1] + cs1);
                float2 o1 = make_float2(d[2] + cs0, d[3] + cs1);
                *reinterpret_cast<float2*>(out + ((size_t)i * N + r) * N + c) = o0;
                *reinterpret_cast<float2*>(out + ((size_t)i * N + r + 8) * N + c) = o1;
            }
}

// ---------------------------------------------------------------------------
extern "C" void kernel_launch(void* const* d_in, const int* in_sizes, int n_in,
                              void* d_out, int out_size) {
    const float* x1 = (const float*)d_in[0];
    const float* x2 = (const float*)d_in[1];
    const float* W  = (const float*)d_in[2];
    const float* b  = (const float*)d_in[3];
    float* out = (float*)d_out;
    (void)in_sizes; (void)n_in; (void)out_size;

    {
        constexpr int SMEM_PREP = 64 * 388 * 4;
        cudaFuncSetAttribute(prep_kernel, cudaFuncAttributeMaxDynamicSharedMemorySize, SMEM_PREP);
        dim3 g(6, 386);
        prep_kernel<<<g, 256, SMEM_PREP>>>(x1, W, b, x2);
    }
    {
        cudaFuncSetAttribute(attn_kernel, cudaFuncAttributeMaxDynamicSharedMemorySize, SMEM_ATTN);
        dim3 g(3, 384);
        attn_kernel<<<g, 512, SMEM_ATTN>>>(out);
    }
}